// round 1
// baseline (speedup 1.0000x reference)
#include <cuda_runtime.h>

#define CB 8
#define CN 2048
#define CD 256
#define CH 4
#define CHD 64
#define CM (CB*CN)      // 16384 rows
#define NT (CN/64)      // 32 tiles of 64

// Scratch (allocation-free rule: __device__ globals)
__device__ float g_Q[CM*CD];
__device__ float g_K[CM*CD];
__device__ float g_V[CM*CD];
__device__ float g_CTX[CM*CD];
__device__ float g_MSG[CM*CD];

// ---------------------------------------------------------------------------
// Generic GEMM: C[M,256] = act( [A | A2] @ W + bias ), M=16384, Nout=256.
// Block tile 128x64, BK=16, 256 threads, 8x4 per thread.
// A rows come from A (k<K1, ld=K1) then A2 (ld=Ktot-K1)  -> fuses the concat.
// ---------------------------------------------------------------------------
__global__ __launch_bounds__(256, 2)
void gemm_kernel(const float* __restrict__ A, const float* __restrict__ A2,
                 const float* __restrict__ W, const float* __restrict__ bias,
                 float* __restrict__ C, int K1, int Ktot, int relu)
{
    __shared__ float As[16][128];   // transposed (k, m)
    __shared__ float Ws[16][64];    // (k, n)
    const int tid = threadIdx.x;
    const int tx = tid & 15, ty = tid >> 4;
    const int m0 = blockIdx.x * 128;
    const int n0 = blockIdx.y * 64;

    float acc[8][4];
    #pragma unroll
    for (int i = 0; i < 8; i++)
        #pragma unroll
        for (int j = 0; j < 4; j++) acc[i][j] = 0.f;

    for (int k0 = 0; k0 < Ktot; k0 += 16) {
        const float* src; int ld;
        if (k0 < K1) { src = A + k0;        ld = K1;        }
        else         { src = A2 + (k0-K1);  ld = Ktot - K1; }
        #pragma unroll
        for (int u = 0; u < 2; u++) {
            int idx = tid + 256 * u;
            int r = idx >> 2, c4 = idx & 3;
            float4 v = *(const float4*)(src + (size_t)(m0 + r) * ld + c4 * 4);
            As[c4*4+0][r] = v.x;
            As[c4*4+1][r] = v.y;
            As[c4*4+2][r] = v.z;
            As[c4*4+3][r] = v.w;
        }
        {
            int r = tid >> 4, c4 = tid & 15;
            *(float4*)&Ws[r][c4*4] =
                *(const float4*)(W + (size_t)(k0 + r) * CD + n0 + c4 * 4);
        }
        __syncthreads();
        #pragma unroll
        for (int kk = 0; kk < 16; kk++) {
            float4 a0 = *(const float4*)&As[kk][ty*8];
            float4 a1 = *(const float4*)&As[kk][ty*8+4];
            float4 b  = *(const float4*)&Ws[kk][tx*4];
            float av[8] = {a0.x,a0.y,a0.z,a0.w,a1.x,a1.y,a1.z,a1.w};
            float bv[4] = {b.x,b.y,b.z,b.w};
            #pragma unroll
            for (int i = 0; i < 8; i++)
                #pragma unroll
                for (int j = 0; j < 4; j++)
                    acc[i][j] = fmaf(av[i], bv[j], acc[i][j]);
        }
        __syncthreads();
    }

    float4 bvec = *(const float4*)(bias + n0 + tx*4);
    float bb[4] = {bvec.x, bvec.y, bvec.z, bvec.w};
    #pragma unroll
    for (int i = 0; i < 8; i++) {
        float4 o;
        o.x = acc[i][0] + bb[0];
        o.y = acc[i][1] + bb[1];
        o.z = acc[i][2] + bb[2];
        o.w = acc[i][3] + bb[3];
        if (relu) {
            o.x = fmaxf(o.x, 0.f); o.y = fmaxf(o.y, 0.f);
            o.z = fmaxf(o.z, 0.f); o.w = fmaxf(o.w, 0.f);
        }
        *(float4*)(C + (size_t)(m0 + ty*8 + i) * CD + n0 + tx*4) = o;
    }
}

// ---------------------------------------------------------------------------
// Flash attention (causal), fp32. One CTA = (b, h, 64-row Q tile).
// 256 threads as 16x16; each thread owns a 4x4 patch of S/P/O.
// Online softmax; stats replicated across the 16-lane row-group via shfl.
// Causal tiles beyond the diagonal are skipped entirely.
// CTX written in [B*N, D] layout (head h -> cols h*64..h*64+63).
// ---------------------------------------------------------------------------
__global__ __launch_bounds__(256, 2)
void attn_kernel(const float* __restrict__ Q, const float* __restrict__ K,
                 const float* __restrict__ V, float* __restrict__ CTX)
{
    extern __shared__ float sm[];
    float* Qs = sm;                 // [64][64] transposed (d, r), pre-scaled
    float* Ks = sm + 4096;          // [64][64] transposed (d, c)
    float* Vs = sm + 8192;          // [64][64] natural   (c, d)
    float* Ps = sm + 12288;         // [64][68] (r, c), pad 68 vs write conflicts

    const int tid = threadIdx.x;
    const int tx = tid & 15, ty = tid >> 4;
    const int qt = (NT - 1) - blockIdx.x;     // heavy tiles scheduled first
    const int h = blockIdx.y, b = blockIdx.z;
    const int q0 = qt * 64;
    const size_t base = ((size_t)b * CN) * CD + (size_t)h * CHD;

    // load Q tile, scaled by 1/sqrt(64), transposed
    {
        const int cid = tid & 15, r0 = tid >> 4;
        #pragma unroll
        for (int p = 0; p < 4; p++) {
            int r = r0 + p * 16;
            float4 v = *(const float4*)(Q + base + (size_t)(q0 + r) * CD + cid * 4);
            Qs[(cid*4+0)*64 + r] = v.x * 0.125f;
            Qs[(cid*4+1)*64 + r] = v.y * 0.125f;
            Qs[(cid*4+2)*64 + r] = v.z * 0.125f;
            Qs[(cid*4+3)*64 + r] = v.w * 0.125f;
        }
    }

    float o[4][4];
    float m[4], l[4];
    #pragma unroll
    for (int i = 0; i < 4; i++) {
        m[i] = -1e30f; l[i] = 0.f;
        #pragma unroll
        for (int j = 0; j < 4; j++) o[i][j] = 0.f;
    }

    for (int kt = 0; kt <= qt; kt++) {
        __syncthreads();  // prev-iter readers of Ks/Vs done; Q load visible (iter 0)
        {
            const int cid = tid & 15, r0 = tid >> 4;
            #pragma unroll
            for (int p = 0; p < 4; p++) {
                int r = r0 + p * 16;
                size_t row = base + (size_t)(kt*64 + r) * CD + cid * 4;
                float4 kv = *(const float4*)(K + row);
                Ks[(cid*4+0)*64 + r] = kv.x;
                Ks[(cid*4+1)*64 + r] = kv.y;
                Ks[(cid*4+2)*64 + r] = kv.z;
                Ks[(cid*4+3)*64 + r] = kv.w;
                float4 vv = *(const float4*)(V + row);
                *(float4*)&Vs[r*64 + cid*4] = vv;
            }
        }
        __syncthreads();

        // S = Qs^T * Ks  (contraction over d)
        float s[4][4];
        #pragma unroll
        for (int i = 0; i < 4; i++)
            #pragma unroll
            for (int j = 0; j < 4; j++) s[i][j] = 0.f;

        #pragma unroll 8
        for (int d = 0; d < 64; d++) {
            float4 qa = *(const float4*)&Qs[d*64 + ty*4];
            float4 kb = *(const float4*)&Ks[d*64 + tx*4];
            float qv[4] = {qa.x, qa.y, qa.z, qa.w};
            float kv[4] = {kb.x, kb.y, kb.z, kb.w};
            #pragma unroll
            for (int i = 0; i < 4; i++)
                #pragma unroll
                for (int j = 0; j < 4; j++)
                    s[i][j] = fmaf(qv[i], kv[j], s[i][j]);
        }

        if (kt == qt) {  // diagonal tile: mask ki > qi (local indices since q0 == kt*64)
            #pragma unroll
            for (int i = 0; i < 4; i++)
                #pragma unroll
                for (int j = 0; j < 4; j++)
                    if (tx*4 + j > ty*4 + i) s[i][j] = -1e30f;
        }

        // online softmax update, write P to smem
        #pragma unroll
        for (int i = 0; i < 4; i++) {
            float v = fmaxf(fmaxf(s[i][0], s[i][1]), fmaxf(s[i][2], s[i][3]));
            v = fmaxf(v, __shfl_xor_sync(0xffffffffu, v, 8));
            v = fmaxf(v, __shfl_xor_sync(0xffffffffu, v, 4));
            v = fmaxf(v, __shfl_xor_sync(0xffffffffu, v, 2));
            v = fmaxf(v, __shfl_xor_sync(0xffffffffu, v, 1));
            float mn = fmaxf(m[i], v);
            float alpha = __expf(m[i] - mn);
            m[i] = mn;
            float p0 = __expf(s[i][0] - mn);
            float p1 = __expf(s[i][1] - mn);
            float p2 = __expf(s[i][2] - mn);
            float p3 = __expf(s[i][3] - mn);
            *(float4*)&Ps[(ty*4+i)*68 + tx*4] = make_float4(p0, p1, p2, p3);
            float sum = (p0 + p1) + (p2 + p3);
            sum += __shfl_xor_sync(0xffffffffu, sum, 8);
            sum += __shfl_xor_sync(0xffffffffu, sum, 4);
            sum += __shfl_xor_sync(0xffffffffu, sum, 2);
            sum += __shfl_xor_sync(0xffffffffu, sum, 1);
            l[i] = l[i] * alpha + sum;
            o[i][0] *= alpha; o[i][1] *= alpha; o[i][2] *= alpha; o[i][3] *= alpha;
        }
        __syncthreads();

        // O += P * V (contraction over key c)
        #pragma unroll 8
        for (int c = 0; c < 64; c++) {
            float4 vb = *(const float4*)&Vs[c*64 + tx*4];
            float vv[4] = {vb.x, vb.y, vb.z, vb.w};
            float pa[4];
            #pragma unroll
            for (int i = 0; i < 4; i++) pa[i] = Ps[(ty*4+i)*68 + c];
            #pragma unroll
            for (int i = 0; i < 4; i++)
                #pragma unroll
                for (int j = 0; j < 4; j++)
                    o[i][j] = fmaf(pa[i], vv[j], o[i][j]);
        }
    }

    #pragma unroll
    for (int i = 0; i < 4; i++) {
        float inv = 1.f / l[i];
        float4 ov = make_float4(o[i][0]*inv, o[i][1]*inv, o[i][2]*inv, o[i][3]*inv);
        *(float4*)(CTX + base + (size_t)(q0 + ty*4 + i) * CD + tx*4) = ov;
    }
}

// ---------------------------------------------------------------------------
extern "C" void kernel_launch(void* const* d_in, const int* in_sizes, int n_in,
                              void* d_out, int out_size)
{
    const float* x  = (const float*)d_in[0];
    // d_in[1] = causal_mask: unused (tril by construction; masking done analytically)
    const float* Wq = (const float*)d_in[2];
    const float* bq = (const float*)d_in[3];
    const float* Wk = (const float*)d_in[4];
    const float* bk = (const float*)d_in[5];
    const float* Wv = (const float*)d_in[6];
    const float* bv = (const float*)d_in[7];
    const float* Wo = (const float*)d_in[8];
    const float* bo = (const float*)d_in[9];
    const float* Wu = (const float*)d_in[10];
    const float* bu = (const float*)d_in[11];
    float* out = (float*)d_out;

    float *Qb, *Kb, *Vb, *Cb, *Mb;
    cudaGetSymbolAddress((void**)&Qb, g_Q);
    cudaGetSymbolAddress((void**)&Kb, g_K);
    cudaGetSymbolAddress((void**)&Vb, g_V);
    cudaGetSymbolAddress((void**)&Cb, g_CTX);
    cudaGetSymbolAddress((void**)&Mb, g_MSG);

    const int attn_smem = 16640 * 4;   // 66,560 B dynamic smem
    cudaFuncSetAttribute(attn_kernel,
                         cudaFuncAttributeMaxDynamicSharedMemorySize, attn_smem);

    dim3 gg(128, 4);   // 16384/128 M-tiles x 256/64 N-tiles

    // Q,K,V projections
    gemm_kernel<<<gg, 256>>>(x, x, Wq, bq, Qb, 256, 256, 0);
    gemm_kernel<<<gg, 256>>>(x, x, Wk, bk, Kb, 256, 256, 0);
    gemm_kernel<<<gg, 256>>>(x, x, Wv, bv, Vb, 256, 256, 0);

    // causal flash attention -> CTX in [B*N, D] layout
    attn_kernel<<<dim3(NT, CH, CB), 256, attn_smem>>>(Qb, Kb, Vb, Cb);

    // messages = CTX @ Wo + bo
    gemm_kernel<<<gg, 256>>>(Cb, Cb, Wo, bo, Mb, 256, 256, 0);

    // out = relu([x | messages] @ Wu + bu)   (concat fused via two-source A)
    gemm_kernel<<<gg, 256>>>(x, Mb, Wu, bu, out, 256, 512, 1);
}

// round 2
// speedup vs baseline: 1.7016x; 1.7016x over previous
#include <cuda_runtime.h>
#include <cstdint>

#define CB 8
#define CN 2048
#define CD 256
#define CH 4
#define CHD 64
#define CM (CB*CN)      // 16384 rows

// Scratch (allocation-free rule: __device__ globals)
__device__ float g_Q[CM*CD];
__device__ float g_K[CM*CD];
__device__ float g_V[CM*CD];
__device__ float g_CTX[CM*CD];
__device__ float g_MSG[CM*CD];

// ---------------------------------------------------------------------------
// Generic GEMM: C[M,256] = act( [A | A2] @ W + bias ), M=16384.
// Block tile 128x64, BK=16, 256 threads, 8x4 per thread. (FFMA roofline)
// ---------------------------------------------------------------------------
__global__ __launch_bounds__(256, 2)
void gemm_kernel(const float* __restrict__ A, const float* __restrict__ A2,
                 const float* __restrict__ W, const float* __restrict__ bias,
                 float* __restrict__ C, int K1, int Ktot, int relu)
{
    __shared__ float As[16][128];
    __shared__ float Ws[16][64];
    const int tid = threadIdx.x;
    const int tx = tid & 15, ty = tid >> 4;
    const int m0 = blockIdx.x * 128;
    const int n0 = blockIdx.y * 64;

    float acc[8][4];
    #pragma unroll
    for (int i = 0; i < 8; i++)
        #pragma unroll
        for (int j = 0; j < 4; j++) acc[i][j] = 0.f;

    for (int k0 = 0; k0 < Ktot; k0 += 16) {
        const float* src; int ld;
        if (k0 < K1) { src = A + k0;        ld = K1;        }
        else         { src = A2 + (k0-K1);  ld = Ktot - K1; }
        #pragma unroll
        for (int u = 0; u < 2; u++) {
            int idx = tid + 256 * u;
            int r = idx >> 2, c4 = idx & 3;
            float4 v = *(const float4*)(src + (size_t)(m0 + r) * ld + c4 * 4);
            As[c4*4+0][r] = v.x;
            As[c4*4+1][r] = v.y;
            As[c4*4+2][r] = v.z;
            As[c4*4+3][r] = v.w;
        }
        {
            int r = tid >> 4, c4 = tid & 15;
            *(float4*)&Ws[r][c4*4] =
                *(const float4*)(W + (size_t)(k0 + r) * CD + n0 + c4 * 4);
        }
        __syncthreads();
        #pragma unroll
        for (int kk = 0; kk < 16; kk++) {
            float4 a0 = *(const float4*)&As[kk][ty*8];
            float4 a1 = *(const float4*)&As[kk][ty*8+4];
            float4 b  = *(const float4*)&Ws[kk][tx*4];
            float av[8] = {a0.x,a0.y,a0.z,a0.w,a1.x,a1.y,a1.z,a1.w};
            float bv[4] = {b.x,b.y,b.z,b.w};
            #pragma unroll
            for (int i = 0; i < 8; i++)
                #pragma unroll
                for (int j = 0; j < 4; j++)
                    acc[i][j] = fmaf(av[i], bv[j], acc[i][j]);
        }
        __syncthreads();
    }

    float4 bvec = *(const float4*)(bias + n0 + tx*4);
    float bb[4] = {bvec.x, bvec.y, bvec.z, bvec.w};
    #pragma unroll
    for (int i = 0; i < 8; i++) {
        float4 o;
        o.x = acc[i][0] + bb[0];
        o.y = acc[i][1] + bb[1];
        o.z = acc[i][2] + bb[2];
        o.w = acc[i][3] + bb[3];
        if (relu) {
            o.x = fmaxf(o.x, 0.f); o.y = fmaxf(o.y, 0.f);
            o.z = fmaxf(o.z, 0.f); o.w = fmaxf(o.w, 0.f);
        }
        *(float4*)(C + (size_t)(m0 + ty*8 + i) * CD + n0 + tx*4) = o;
    }
}

// ---------------------------------------------------------------------------
// tf32 mma.sync helpers
// ---------------------------------------------------------------------------
__device__ __forceinline__ uint32_t f2tf32(float f) {
    uint32_t u;
    asm("cvt.rna.tf32.f32 %0, %1;" : "=r"(u) : "f"(f));
    return u;
}

__device__ __forceinline__ void mma_tf32(float c[4],
                                         uint32_t a0, uint32_t a1, uint32_t a2, uint32_t a3,
                                         uint32_t b0, uint32_t b1)
{
    asm volatile(
        "mma.sync.aligned.m16n8k8.row.col.f32.tf32.tf32.f32 "
        "{%0,%1,%2,%3}, {%4,%5,%6,%7}, {%8,%9}, {%0,%1,%2,%3};\n"
        : "+f"(c[0]), "+f"(c[1]), "+f"(c[2]), "+f"(c[3])
        : "r"(a0), "r"(a1), "r"(a2), "r"(a3), "r"(b0), "r"(b1));
}

// ---------------------------------------------------------------------------
// Flash attention (causal), tf32 tensor cores.
// CTA = (b, h, 128-row Q tile). 8 warps; warp w owns rows w*16..w*16+15.
// Q fragments kept in registers for the whole K loop. K/V tiles (64 keys)
// staged in smem as tf32 bits; P round-trips through smem (warp-local).
// Strides: Ks 68 (bank = 4g+8kc+t, conflict-free), Vs 72 (8t+g), Ps 68.
// ---------------------------------------------------------------------------
#define KS_STR 68
#define VS_STR 72
#define PS_STR 68
#define SMEM_ATTN ((64*KS_STR + 64*VS_STR + 128*PS_STR) * 4)

__global__ __launch_bounds__(256, 2)
void attn_mma_kernel(const float* __restrict__ Q, const float* __restrict__ K,
                     const float* __restrict__ V, float* __restrict__ CTX)
{
    extern __shared__ uint32_t sm_u[];
    uint32_t* Ks = sm_u;                       // [64][KS_STR] tf32 bits (key, d)
    uint32_t* Vs = sm_u + 64*KS_STR;           // [64][VS_STR] tf32 bits (key, d)
    uint32_t* Ps = sm_u + 64*KS_STR + 64*VS_STR; // [128][PS_STR] tf32 bits (row, key)

    const int tid  = threadIdx.x;
    const int lane = tid & 31;
    const int w    = tid >> 5;
    const int g    = lane >> 2;       // group id (row within fragment)
    const int t    = lane & 3;        // thread-in-group (col)

    const int qb = (CN/128 - 1) - blockIdx.x;   // heavy tiles first
    const int q0 = qb * 128;
    const int h = blockIdx.y, b = blockIdx.z;
    const size_t base = ((size_t)b * CN) * CD + (size_t)h * CHD;

    const int rowA = q0 + w*16 + g;   // global rows owned by this thread
    const int rowB = rowA + 8;

    // ---- Q fragments (scaled by 1/sqrt(64)), registers for entire loop ----
    uint32_t qa[8][4];
    #pragma unroll
    for (int kc = 0; kc < 8; kc++) {
        int col = kc*8 + t;
        qa[kc][0] = f2tf32(Q[base + (size_t)rowA*CD + col    ] * 0.125f);
        qa[kc][1] = f2tf32(Q[base + (size_t)rowB*CD + col    ] * 0.125f);
        qa[kc][2] = f2tf32(Q[base + (size_t)rowA*CD + col + 4] * 0.125f);
        qa[kc][3] = f2tf32(Q[base + (size_t)rowB*CD + col + 4] * 0.125f);
    }

    float of[8][4];
    #pragma unroll
    for (int j = 0; j < 8; j++)
        #pragma unroll
        for (int e = 0; e < 4; e++) of[j][e] = 0.f;
    float mA = -1e30f, mB = -1e30f, lA = 0.f, lB = 0.f;

    const int nkt = 2*qb + 2;
    for (int kt = 0; kt < nkt; kt++) {
        __syncthreads();
        // ---- stage K,V tile (64 keys x 64 d) as tf32 bits ----
        {
            const int r = tid >> 2;
            const int cb = (tid & 3) * 16;
            #pragma unroll
            for (int p = 0; p < 4; p++) {
                int c = cb + p*4;
                size_t grow = base + (size_t)(kt*64 + r) * CD + c;
                float4 kv = *(const float4*)(K + grow);
                Ks[r*KS_STR + c + 0] = f2tf32(kv.x);
                Ks[r*KS_STR + c + 1] = f2tf32(kv.y);
                Ks[r*KS_STR + c + 2] = f2tf32(kv.z);
                Ks[r*KS_STR + c + 3] = f2tf32(kv.w);
                float4 vv = *(const float4*)(V + grow);
                Vs[r*VS_STR + c + 0] = f2tf32(vv.x);
                Vs[r*VS_STR + c + 1] = f2tf32(vv.y);
                Vs[r*VS_STR + c + 2] = f2tf32(vv.z);
                Vs[r*VS_STR + c + 3] = f2tf32(vv.w);
            }
        }
        __syncthreads();

        // warp fully above diagonal? skip (P would be all zero)
        if (kt*64 > q0 + w*16 + 15) continue;

        // ---- S = Q K^T (16x64 per warp) ----
        float sc[8][4];
        #pragma unroll
        for (int j = 0; j < 8; j++)
            #pragma unroll
            for (int e = 0; e < 4; e++) sc[j][e] = 0.f;

        #pragma unroll
        for (int kc = 0; kc < 8; kc++) {
            #pragma unroll
            for (int j = 0; j < 8; j++) {
                uint32_t b0 = Ks[(j*8 + g)*KS_STR + kc*8 + t];
                uint32_t b1 = Ks[(j*8 + g)*KS_STR + kc*8 + t + 4];
                mma_tf32(sc[j], qa[kc][0], qa[kc][1], qa[kc][2], qa[kc][3], b0, b1);
            }
        }

        // ---- causal mask (only on diagonal-overlapping tiles) ----
        if (kt*64 + 63 > q0 + w*16) {
            #pragma unroll
            for (int j = 0; j < 8; j++) {
                int c0 = kt*64 + j*8 + t*2;
                int c1 = c0 + 1;
                if (c0 > rowA) sc[j][0] = -1e30f;
                if (c1 > rowA) sc[j][1] = -1e30f;
                if (c0 > rowB) sc[j][2] = -1e30f;
                if (c1 > rowB) sc[j][3] = -1e30f;
            }
        }

        // ---- online softmax (rows rowA, rowB; warp-local) ----
        float mxA = -1e30f, mxB = -1e30f;
        #pragma unroll
        for (int j = 0; j < 8; j++) {
            mxA = fmaxf(mxA, fmaxf(sc[j][0], sc[j][1]));
            mxB = fmaxf(mxB, fmaxf(sc[j][2], sc[j][3]));
        }
        mxA = fmaxf(mxA, __shfl_xor_sync(0xffffffffu, mxA, 1));
        mxA = fmaxf(mxA, __shfl_xor_sync(0xffffffffu, mxA, 2));
        mxB = fmaxf(mxB, __shfl_xor_sync(0xffffffffu, mxB, 1));
        mxB = fmaxf(mxB, __shfl_xor_sync(0xffffffffu, mxB, 2));

        float nmA = fmaxf(mA, mxA), nmB = fmaxf(mB, mxB);
        float alA = __expf(mA - nmA), alB = __expf(mB - nmB);
        mA = nmA; mB = nmB;

        float sumA = 0.f, sumB = 0.f;
        #pragma unroll
        for (int j = 0; j < 8; j++) {
            float p0 = __expf(sc[j][0] - mA);
            float p1 = __expf(sc[j][1] - mA);
            float p2 = __expf(sc[j][2] - mB);
            float p3 = __expf(sc[j][3] - mB);
            sumA += p0 + p1;
            sumB += p2 + p3;
            uint32_t* pr0 = &Ps[(w*16 + g    )*PS_STR + j*8 + t*2];
            uint32_t* pr1 = &Ps[(w*16 + g + 8)*PS_STR + j*8 + t*2];
            pr0[0] = f2tf32(p0); pr0[1] = f2tf32(p1);
            pr1[0] = f2tf32(p2); pr1[1] = f2tf32(p3);
        }
        sumA += __shfl_xor_sync(0xffffffffu, sumA, 1);
        sumA += __shfl_xor_sync(0xffffffffu, sumA, 2);
        sumB += __shfl_xor_sync(0xffffffffu, sumB, 1);
        sumB += __shfl_xor_sync(0xffffffffu, sumB, 2);
        lA = lA * alA + sumA;
        lB = lB * alB + sumB;

        #pragma unroll
        for (int j = 0; j < 8; j++) {
            of[j][0] *= alA; of[j][1] *= alA;
            of[j][2] *= alB; of[j][3] *= alB;
        }
        __syncwarp();

        // ---- O += P V (P fragments from smem, warp-local rows) ----
        #pragma unroll
        for (int kc = 0; kc < 8; kc++) {
            uint32_t a0 = Ps[(w*16 + g    )*PS_STR + kc*8 + t    ];
            uint32_t a1 = Ps[(w*16 + g + 8)*PS_STR + kc*8 + t    ];
            uint32_t a2 = Ps[(w*16 + g    )*PS_STR + kc*8 + t + 4];
            uint32_t a3 = Ps[(w*16 + g + 8)*PS_STR + kc*8 + t + 4];
            #pragma unroll
            for (int j = 0; j < 8; j++) {
                uint32_t b0 = Vs[(kc*8 + t    )*VS_STR + j*8 + g];
                uint32_t b1 = Vs[(kc*8 + t + 4)*VS_STR + j*8 + g];
                mma_tf32(of[j], a0, a1, a2, a3, b0, b1);
            }
        }
    }

    // ---- epilogue: normalize, write CTX ([B*N, D], head h at cols h*64) ----
    float invA = 1.f / lA, invB = 1.f / lB;
    #pragma unroll
    for (int j = 0; j < 8; j++) {
        float2 oA = make_float2(of[j][0]*invA, of[j][1]*invA);
        float2 oB = make_float2(of[j][2]*invB, of[j][3]*invB);
        *(float2*)(CTX + base + (size_t)rowA*CD + j*8 + t*2) = oA;
        *(float2*)(CTX + base + (size_t)rowB*CD + j*8 + t*2) = oB;
    }
}

// ---------------------------------------------------------------------------
extern "C" void kernel_launch(void* const* d_in, const int* in_sizes, int n_in,
                              void* d_out, int out_size)
{
    const float* x  = (const float*)d_in[0];
    // d_in[1] = causal_mask: unused (tril by construction; handled analytically)
    const float* Wq = (const float*)d_in[2];
    const float* bq = (const float*)d_in[3];
    const float* Wk = (const float*)d_in[4];
    const float* bk = (const float*)d_in[5];
    const float* Wv = (const float*)d_in[6];
    const float* bv = (const float*)d_in[7];
    const float* Wo = (const float*)d_in[8];
    const float* bo = (const float*)d_in[9];
    const float* Wu = (const float*)d_in[10];
    const float* bu = (const float*)d_in[11];
    float* out = (float*)d_out;

    float *Qb, *Kb, *Vb, *Cb, *Mb;
    cudaGetSymbolAddress((void**)&Qb, g_Q);
    cudaGetSymbolAddress((void**)&Kb, g_K);
    cudaGetSymbolAddress((void**)&Vb, g_V);
    cudaGetSymbolAddress((void**)&Cb, g_CTX);
    cudaGetSymbolAddress((void**)&Mb, g_MSG);

    cudaFuncSetAttribute(attn_mma_kernel,
                         cudaFuncAttributeMaxDynamicSharedMemorySize, SMEM_ATTN);

    dim3 gg(128, 4);   // 16384/128 M-tiles x 256/64 N-tiles

    gemm_kernel<<<gg, 256>>>(x, x, Wq, bq, Qb, 256, 256, 0);
    gemm_kernel<<<gg, 256>>>(x, x, Wk, bk, Kb, 256, 256, 0);
    gemm_kernel<<<gg, 256>>>(x, x, Wv, bv, Vb, 256, 256, 0);

    attn_mma_kernel<<<dim3(CN/128, CH, CB), 256, SMEM_ATTN>>>(Qb, Kb, Vb, Cb);

    gemm_kernel<<<gg, 256>>>(Cb, Cb, Wo, bo, Mb, 256, 256, 0);
    gemm_kernel<<<gg, 256>>>(x, Mb, Wu, bu, out, 256, 512, 1);
}

// round 3
// speedup vs baseline: 2.8312x; 1.6639x over previous
#include <cuda_runtime.h>
#include <cstdint>

#define CB 8
#define CN 2048
#define CD 256
#define CH 4
#define CHD 64
#define CM (CB*CN)      // 16384 rows

// Scratch (allocation-free rule: __device__ globals)
__device__ float g_Q[CM*CD];
__device__ float g_K[CM*CD];
__device__ float g_V[CM*CD];
__device__ float g_CTX[CM*CD];
__device__ float g_MSG[CM*CD];

// ---------------------------------------------------------------------------
// tf32 helpers
// ---------------------------------------------------------------------------
__device__ __forceinline__ uint32_t f2tf32(float f) {
    uint32_t u;
    asm("cvt.rna.tf32.f32 %0, %1;" : "=r"(u) : "f"(f));
    return u;
}

__device__ __forceinline__ void mma_tf32(float c[4],
                                         uint32_t a0, uint32_t a1, uint32_t a2, uint32_t a3,
                                         uint32_t b0, uint32_t b1)
{
    asm volatile(
        "mma.sync.aligned.m16n8k8.row.col.f32.tf32.tf32.f32 "
        "{%0,%1,%2,%3}, {%4,%5,%6,%7}, {%8,%9}, {%0,%1,%2,%3};\n"
        : "+f"(c[0]), "+f"(c[1]), "+f"(c[2]), "+f"(c[3])
        : "r"(a0), "r"(a1), "r"(a2), "r"(a3), "r"(b0), "r"(b1));
}

// ---------------------------------------------------------------------------
// tf32 tensor-core GEMM: C[M,256] = act( [A | A2] @ W + bias ).
// CTA tile 128x128, BK=32, 8 warps (2x4), warp tile 64x32 (4x4 m16n8k8).
// As[m][k] stride 36  -> frag bank 4g+t (conflict-free)
// Bs[k][n] stride 136 -> frag bank 8t+g (conflict-free)
// ---------------------------------------------------------------------------
__global__ __launch_bounds__(256, 2)
void gemm_tf32_kernel(const float* __restrict__ A, const float* __restrict__ A2,
                      const float* __restrict__ W, const float* __restrict__ bias,
                      float* __restrict__ C, int K1, int Ktot, int relu)
{
    __shared__ uint32_t As[128*36];
    __shared__ uint32_t Bs[32*136];

    const int tid  = threadIdx.x;
    const int lane = tid & 31;
    const int w    = tid >> 5;
    const int g    = lane >> 2;
    const int t    = lane & 3;
    const int m0 = blockIdx.x * 128;
    const int n0 = blockIdx.y * 128;
    const int warpM = (w >> 2) * 64;
    const int warpN = (w & 3) * 32;

    float acc[4][4][4];
    #pragma unroll
    for (int mi = 0; mi < 4; mi++)
        #pragma unroll
        for (int ni = 0; ni < 4; ni++)
            #pragma unroll
            for (int e = 0; e < 4; e++) acc[mi][ni][e] = 0.f;

    for (int k0 = 0; k0 < Ktot; k0 += 32) {
        const float* src; int ld;
        if (k0 < K1) { src = A + k0;        ld = K1;        }
        else         { src = A2 + (k0-K1);  ld = Ktot - K1; }

        // stage A tile 128x32 (coalesced; conflict-free float4 smem stores)
        #pragma unroll
        for (int u = 0; u < 4; u++) {
            int f = tid + 256*u;
            int r = f >> 3, c4 = f & 7;
            float4 v = *(const float4*)(src + (size_t)(m0 + r) * ld + c4*4);
            uint32_t* dst = &As[r*36 + c4*4];
            dst[0] = f2tf32(v.x); dst[1] = f2tf32(v.y);
            dst[2] = f2tf32(v.z); dst[3] = f2tf32(v.w);
        }
        // stage B tile 32x128 (one row per warp, coalesced)
        #pragma unroll
        for (int u = 0; u < 4; u++) {
            int f = tid + 256*u;
            int kr = f >> 5, c4 = f & 31;
            float4 v = *(const float4*)(W + (size_t)(k0 + kr) * CD + n0 + c4*4);
            uint32_t* dst = &Bs[kr*136 + c4*4];
            dst[0] = f2tf32(v.x); dst[1] = f2tf32(v.y);
            dst[2] = f2tf32(v.z); dst[3] = f2tf32(v.w);
        }
        __syncthreads();

        #pragma unroll
        for (int kk = 0; kk < 32; kk += 8) {
            uint32_t af[4][4];
            #pragma unroll
            for (int mi = 0; mi < 4; mi++) {
                int m = warpM + mi*16;
                af[mi][0] = As[(m + g    )*36 + kk + t    ];
                af[mi][1] = As[(m + g + 8)*36 + kk + t    ];
                af[mi][2] = As[(m + g    )*36 + kk + t + 4];
                af[mi][3] = As[(m + g + 8)*36 + kk + t + 4];
            }
            uint32_t bf[4][2];
            #pragma unroll
            for (int ni = 0; ni < 4; ni++) {
                int n = warpN + ni*8;
                bf[ni][0] = Bs[(kk + t    )*136 + n + g];
                bf[ni][1] = Bs[(kk + t + 4)*136 + n + g];
            }
            #pragma unroll
            for (int mi = 0; mi < 4; mi++)
                #pragma unroll
                for (int ni = 0; ni < 4; ni++)
                    mma_tf32(acc[mi][ni], af[mi][0], af[mi][1], af[mi][2], af[mi][3],
                             bf[ni][0], bf[ni][1]);
        }
        __syncthreads();
    }

    // epilogue: bias (+ReLU), write C
    #pragma unroll
    for (int ni = 0; ni < 4; ni++) {
        int col = n0 + warpN + ni*8 + t*2;
        float bx = bias[col], by = bias[col + 1];
        #pragma unroll
        for (int mi = 0; mi < 4; mi++) {
            int row = m0 + warpM + mi*16;
            float v0 = acc[mi][ni][0] + bx;
            float v1 = acc[mi][ni][1] + by;
            float v2 = acc[mi][ni][2] + bx;
            float v3 = acc[mi][ni][3] + by;
            if (relu) {
                v0 = fmaxf(v0, 0.f); v1 = fmaxf(v1, 0.f);
                v2 = fmaxf(v2, 0.f); v3 = fmaxf(v3, 0.f);
            }
            *(float2*)(C + (size_t)(row + g    ) * CD + col) = make_float2(v0, v1);
            *(float2*)(C + (size_t)(row + g + 8) * CD + col) = make_float2(v2, v3);
        }
    }
}

// ---------------------------------------------------------------------------
// Flash attention (causal), tf32 tensor cores. (unchanged from round 2)
// CTA = (b, h, 128-row Q tile). 8 warps; warp w owns rows w*16..w*16+15.
// ---------------------------------------------------------------------------
#define KS_STR 68
#define VS_STR 72
#define PS_STR 68
#define SMEM_ATTN ((64*KS_STR + 64*VS_STR + 128*PS_STR) * 4)

__global__ __launch_bounds__(256, 2)
void attn_mma_kernel(const float* __restrict__ Q, const float* __restrict__ K,
                     const float* __restrict__ V, float* __restrict__ CTX)
{
    extern __shared__ uint32_t sm_u[];
    uint32_t* Ks = sm_u;
    uint32_t* Vs = sm_u + 64*KS_STR;
    uint32_t* Ps = sm_u + 64*KS_STR + 64*VS_STR;

    const int tid  = threadIdx.x;
    const int lane = tid & 31;
    const int w    = tid >> 5;
    const int g    = lane >> 2;
    const int t    = lane & 3;

    const int qb = (CN/128 - 1) - blockIdx.x;
    const int q0 = qb * 128;
    const int h = blockIdx.y, b = blockIdx.z;
    const size_t base = ((size_t)b * CN) * CD + (size_t)h * CHD;

    const int rowA = q0 + w*16 + g;
    const int rowB = rowA + 8;

    uint32_t qa[8][4];
    #pragma unroll
    for (int kc = 0; kc < 8; kc++) {
        int col = kc*8 + t;
        qa[kc][0] = f2tf32(Q[base + (size_t)rowA*CD + col    ] * 0.125f);
        qa[kc][1] = f2tf32(Q[base + (size_t)rowB*CD + col    ] * 0.125f);
        qa[kc][2] = f2tf32(Q[base + (size_t)rowA*CD + col + 4] * 0.125f);
        qa[kc][3] = f2tf32(Q[base + (size_t)rowB*CD + col + 4] * 0.125f);
    }

    float of[8][4];
    #pragma unroll
    for (int j = 0; j < 8; j++)
        #pragma unroll
        for (int e = 0; e < 4; e++) of[j][e] = 0.f;
    float mA = -1e30f, mB = -1e30f, lA = 0.f, lB = 0.f;

    const int nkt = 2*qb + 2;
    for (int kt = 0; kt < nkt; kt++) {
        __syncthreads();
        {
            const int r = tid >> 2;
            const int cb = (tid & 3) * 16;
            #pragma unroll
            for (int p = 0; p < 4; p++) {
                int c = cb + p*4;
                size_t grow = base + (size_t)(kt*64 + r) * CD + c;
                float4 kv = *(const float4*)(K + grow);
                Ks[r*KS_STR + c + 0] = f2tf32(kv.x);
                Ks[r*KS_STR + c + 1] = f2tf32(kv.y);
                Ks[r*KS_STR + c + 2] = f2tf32(kv.z);
                Ks[r*KS_STR + c + 3] = f2tf32(kv.w);
                float4 vv = *(const float4*)(V + grow);
                Vs[r*VS_STR + c + 0] = f2tf32(vv.x);
                Vs[r*VS_STR + c + 1] = f2tf32(vv.y);
                Vs[r*VS_STR + c + 2] = f2tf32(vv.z);
                Vs[r*VS_STR + c + 3] = f2tf32(vv.w);
            }
        }
        __syncthreads();

        if (kt*64 > q0 + w*16 + 15) continue;

        float sc[8][4];
        #pragma unroll
        for (int j = 0; j < 8; j++)
            #pragma unroll
            for (int e = 0; e < 4; e++) sc[j][e] = 0.f;

        #pragma unroll
        for (int kc = 0; kc < 8; kc++) {
            #pragma unroll
            for (int j = 0; j < 8; j++) {
                uint32_t b0 = Ks[(j*8 + g)*KS_STR + kc*8 + t];
                uint32_t b1 = Ks[(j*8 + g)*KS_STR + kc*8 + t + 4];
                mma_tf32(sc[j], qa[kc][0], qa[kc][1], qa[kc][2], qa[kc][3], b0, b1);
            }
        }

        if (kt*64 + 63 > q0 + w*16) {
            #pragma unroll
            for (int j = 0; j < 8; j++) {
                int c0 = kt*64 + j*8 + t*2;
                int c1 = c0 + 1;
                if (c0 > rowA) sc[j][0] = -1e30f;
                if (c1 > rowA) sc[j][1] = -1e30f;
                if (c0 > rowB) sc[j][2] = -1e30f;
                if (c1 > rowB) sc[j][3] = -1e30f;
            }
        }

        float mxA = -1e30f, mxB = -1e30f;
        #pragma unroll
        for (int j = 0; j < 8; j++) {
            mxA = fmaxf(mxA, fmaxf(sc[j][0], sc[j][1]));
            mxB = fmaxf(mxB, fmaxf(sc[j][2], sc[j][3]));
        }
        mxA = fmaxf(mxA, __shfl_xor_sync(0xffffffffu, mxA, 1));
        mxA = fmaxf(mxA, __shfl_xor_sync(0xffffffffu, mxA, 2));
        mxB = fmaxf(mxB, __shfl_xor_sync(0xffffffffu, mxB, 1));
        mxB = fmaxf(mxB, __shfl_xor_sync(0xffffffffu, mxB, 2));

        float nmA = fmaxf(mA, mxA), nmB = fmaxf(mB, mxB);
        float alA = __expf(mA - nmA), alB = __expf(mB - nmB);
        mA = nmA; mB = nmB;

        float sumA = 0.f, sumB = 0.f;
        #pragma unroll
        for (int j = 0; j < 8; j++) {
            float p0 = __expf(sc[j][0] - mA);
            float p1 = __expf(sc[j][1] - mA);
            float p2 = __expf(sc[j][2] - mB);
            float p3 = __expf(sc[j][3] - mB);
            sumA += p0 + p1;
            sumB += p2 + p3;
            uint32_t* pr0 = &Ps[(w*16 + g    )*PS_STR + j*8 + t*2];
            uint32_t* pr1 = &Ps[(w*16 + g + 8)*PS_STR + j*8 + t*2];
            pr0[0] = f2tf32(p0); pr0[1] = f2tf32(p1);
            pr1[0] = f2tf32(p2); pr1[1] = f2tf32(p3);
        }
        sumA += __shfl_xor_sync(0xffffffffu, sumA, 1);
        sumA += __shfl_xor_sync(0xffffffffu, sumA, 2);
        sumB += __shfl_xor_sync(0xffffffffu, sumB, 1);
        sumB += __shfl_xor_sync(0xffffffffu, sumB, 2);
        lA = lA * alA + sumA;
        lB = lB * alB + sumB;

        #pragma unroll
        for (int j = 0; j < 8; j++) {
            of[j][0] *= alA; of[j][1] *= alA;
            of[j][2] *= alB; of[j][3] *= alB;
        }
        __syncwarp();

        #pragma unroll
        for (int kc = 0; kc < 8; kc++) {
            uint32_t a0 = Ps[(w*16 + g    )*PS_STR + kc*8 + t    ];
            uint32_t a1 = Ps[(w*16 + g + 8)*PS_STR + kc*8 + t    ];
            uint32_t a2 = Ps[(w*16 + g    )*PS_STR + kc*8 + t + 4];
            uint32_t a3 = Ps[(w*16 + g + 8)*PS_STR + kc*8 + t + 4];
            #pragma unroll
            for (int j = 0; j < 8; j++) {
                uint32_t b0 = Vs[(kc*8 + t    )*VS_STR + j*8 + g];
                uint32_t b1 = Vs[(kc*8 + t + 4)*VS_STR + j*8 + g];
                mma_tf32(of[j], a0, a1, a2, a3, b0, b1);
            }
        }
    }

    float invA = 1.f / lA, invB = 1.f / lB;
    #pragma unroll
    for (int j = 0; j < 8; j++) {
        float2 oA = make_float2(of[j][0]*invA, of[j][1]*invA);
        float2 oB = make_float2(of[j][2]*invB, of[j][3]*invB);
        *(float2*)(CTX + base + (size_t)rowA*CD + j*8 + t*2) = oA;
        *(float2*)(CTX + base + (size_t)rowB*CD + j*8 + t*2) = oB;
    }
}

// ---------------------------------------------------------------------------
extern "C" void kernel_launch(void* const* d_in, const int* in_sizes, int n_in,
                              void* d_out, int out_size)
{
    const float* x  = (const float*)d_in[0];
    // d_in[1] = causal_mask: unused (tril by construction; handled analytically)
    const float* Wq = (const float*)d_in[2];
    const float* bq = (const float*)d_in[3];
    const float* Wk = (const float*)d_in[4];
    const float* bk = (const float*)d_in[5];
    const float* Wv = (const float*)d_in[6];
    const float* bv = (const float*)d_in[7];
    const float* Wo = (const float*)d_in[8];
    const float* bo = (const float*)d_in[9];
    const float* Wu = (const float*)d_in[10];
    const float* bu = (const float*)d_in[11];
    float* out = (float*)d_out;

    float *Qb, *Kb, *Vb, *Cb, *Mb;
    cudaGetSymbolAddress((void**)&Qb, g_Q);
    cudaGetSymbolAddress((void**)&Kb, g_K);
    cudaGetSymbolAddress((void**)&Vb, g_V);
    cudaGetSymbolAddress((void**)&Cb, g_CTX);
    cudaGetSymbolAddress((void**)&Mb, g_MSG);

    cudaFuncSetAttribute(attn_mma_kernel,
                         cudaFuncAttributeMaxDynamicSharedMemorySize, SMEM_ATTN);

    dim3 gg(CM/128, CD/128);   // 128 x 2

    gemm_tf32_kernel<<<gg, 256>>>(x, x, Wq, bq, Qb, 256, 256, 0);
    gemm_tf32_kernel<<<gg, 256>>>(x, x, Wk, bk, Kb, 256, 256, 0);
    gemm_tf32_kernel<<<gg, 256>>>(x, x, Wv, bv, Vb, 256, 256, 0);

    attn_mma_kernel<<<dim3(CN/128, CH, CB), 256, SMEM_ATTN>>>(Qb, Kb, Vb, Cb);

    gemm_tf32_kernel<<<gg, 256>>>(Cb, Cb, Wo, bo, Mb, 256, 256, 0);
    gemm_tf32_kernel<<<gg, 256>>>(x, Mb, Wu, bu, out, 256, 512, 1);
}

// round 4
// speedup vs baseline: 3.3718x; 1.1909x over previous
#include <cuda_runtime.h>
#include <cstdint>

#define CB 8
#define CN 2048
#define CD 256
#define CH 4
#define CHD 64
#define CM (CB*CN)      // 16384 rows
#define NKT (CN/64)     // 32 key tiles per (b,h)

// Scratch (allocation-free rule: __device__ globals)
__device__ float    g_Q[CM*CD];
__device__ uint32_t g_Kt[CM*CD];    // tf32 bits, (b,h,kt) 64x64 tiles
__device__ uint32_t g_Vt[CM*CD];    // tf32 bits, (b,h,kt) 64x64 tiles
__device__ float    g_CTX[CM*CD];
__device__ float    g_MSG[CM*CD];

// ---------------------------------------------------------------------------
// tf32 helpers
// ---------------------------------------------------------------------------
__device__ __forceinline__ uint32_t f2tf32(float f) {
    uint32_t u;
    asm("cvt.rna.tf32.f32 %0, %1;" : "=r"(u) : "f"(f));
    return u;
}

__device__ __forceinline__ void mma_tf32(float c[4],
                                         uint32_t a0, uint32_t a1, uint32_t a2, uint32_t a3,
                                         uint32_t b0, uint32_t b1)
{
    asm volatile(
        "mma.sync.aligned.m16n8k8.row.col.f32.tf32.tf32.f32 "
        "{%0,%1,%2,%3}, {%4,%5,%6,%7}, {%8,%9}, {%0,%1,%2,%3};\n"
        : "+f"(c[0]), "+f"(c[1]), "+f"(c[2]), "+f"(c[3])
        : "r"(a0), "r"(a1), "r"(a2), "r"(a3), "r"(b0), "r"(b1));
}

__device__ __forceinline__ void cp16(uint32_t smem_addr, const void* gptr) {
    asm volatile("cp.async.cg.shared.global [%0], [%1], 16;"
                 :: "r"(smem_addr), "l"(gptr));
}

// tiled tf32 K/V index: (b, h, kt) tile of 64x64, row-major inside
__device__ __forceinline__ size_t kv_idx(int row, int col) {
    return ((size_t)((row >> 11) * CH + (col >> 6)) * NKT + ((row & 2047) >> 6)) * 4096
           + (size_t)(row & 63) * 64 + (col & 63);
}

// ---------------------------------------------------------------------------
// tf32 tensor-core GEMM: C = act( [A | A2] @ W + bias ).
// CTA tile 128x128, BK=32, 8 warps, warp tile 64x32 (4x4 m16n8k8).
// mode: 0 = fp32 [M,256] out; 1 = same + ReLU; 2 = tf32-tiled KV out.
// ---------------------------------------------------------------------------
__global__ __launch_bounds__(256, 2)
void gemm_tf32_kernel(const float* __restrict__ A, const float* __restrict__ A2,
                      const float* __restrict__ W, const float* __restrict__ bias,
                      float* __restrict__ C, int K1, int Ktot, int mode)
{
    __shared__ uint32_t As[128*36];
    __shared__ uint32_t Bs[32*136];

    const int tid  = threadIdx.x;
    const int lane = tid & 31;
    const int w    = tid >> 5;
    const int g    = lane >> 2;
    const int t    = lane & 3;
    const int m0 = blockIdx.x * 128;
    const int n0 = blockIdx.y * 128;
    const int warpM = (w >> 2) * 64;
    const int warpN = (w & 3) * 32;

    float acc[4][4][4];
    #pragma unroll
    for (int mi = 0; mi < 4; mi++)
        #pragma unroll
        for (int ni = 0; ni < 4; ni++)
            #pragma unroll
            for (int e = 0; e < 4; e++) acc[mi][ni][e] = 0.f;

    for (int k0 = 0; k0 < Ktot; k0 += 32) {
        const float* src; int ld;
        if (k0 < K1) { src = A + k0;        ld = K1;        }
        else         { src = A2 + (k0-K1);  ld = Ktot - K1; }

        #pragma unroll
        for (int u = 0; u < 4; u++) {
            int f = tid + 256*u;
            int r = f >> 3, c4 = f & 7;
            float4 v = *(const float4*)(src + (size_t)(m0 + r) * ld + c4*4);
            uint32_t* dst = &As[r*36 + c4*4];
            dst[0] = f2tf32(v.x); dst[1] = f2tf32(v.y);
            dst[2] = f2tf32(v.z); dst[3] = f2tf32(v.w);
        }
        #pragma unroll
        for (int u = 0; u < 4; u++) {
            int f = tid + 256*u;
            int kr = f >> 5, c4 = f & 31;
            float4 v = *(const float4*)(W + (size_t)(k0 + kr) * CD + n0 + c4*4);
            uint32_t* dst = &Bs[kr*136 + c4*4];
            dst[0] = f2tf32(v.x); dst[1] = f2tf32(v.y);
            dst[2] = f2tf32(v.z); dst[3] = f2tf32(v.w);
        }
        __syncthreads();

        #pragma unroll
        for (int kk = 0; kk < 32; kk += 8) {
            uint32_t af[4][4];
            #pragma unroll
            for (int mi = 0; mi < 4; mi++) {
                int m = warpM + mi*16;
                af[mi][0] = As[(m + g    )*36 + kk + t    ];
                af[mi][1] = As[(m + g + 8)*36 + kk + t    ];
                af[mi][2] = As[(m + g    )*36 + kk + t + 4];
                af[mi][3] = As[(m + g + 8)*36 + kk + t + 4];
            }
            uint32_t bf[4][2];
            #pragma unroll
            for (int ni = 0; ni < 4; ni++) {
                int n = warpN + ni*8;
                bf[ni][0] = Bs[(kk + t    )*136 + n + g];
                bf[ni][1] = Bs[(kk + t + 4)*136 + n + g];
            }
            #pragma unroll
            for (int mi = 0; mi < 4; mi++)
                #pragma unroll
                for (int ni = 0; ni < 4; ni++)
                    mma_tf32(acc[mi][ni], af[mi][0], af[mi][1], af[mi][2], af[mi][3],
                             bf[ni][0], bf[ni][1]);
        }
        __syncthreads();
    }

    // epilogue
    if (mode == 2) {
        uint32_t* Ct = (uint32_t*)C;
        #pragma unroll
        for (int ni = 0; ni < 4; ni++) {
            int col = n0 + warpN + ni*8 + t*2;
            float bx = bias[col], by = bias[col + 1];
            #pragma unroll
            for (int mi = 0; mi < 4; mi++) {
                int r0 = m0 + warpM + mi*16 + g;
                int r1 = r0 + 8;
                size_t i0 = kv_idx(r0, col);
                Ct[i0    ] = f2tf32(acc[mi][ni][0] + bx);
                Ct[i0 + 1] = f2tf32(acc[mi][ni][1] + by);
                size_t i1 = kv_idx(r1, col);
                Ct[i1    ] = f2tf32(acc[mi][ni][2] + bx);
                Ct[i1 + 1] = f2tf32(acc[mi][ni][3] + by);
            }
        }
    } else {
        #pragma unroll
        for (int ni = 0; ni < 4; ni++) {
            int col = n0 + warpN + ni*8 + t*2;
            float bx = bias[col], by = bias[col + 1];
            #pragma unroll
            for (int mi = 0; mi < 4; mi++) {
                int row = m0 + warpM + mi*16;
                float v0 = acc[mi][ni][0] + bx;
                float v1 = acc[mi][ni][1] + by;
                float v2 = acc[mi][ni][2] + bx;
                float v3 = acc[mi][ni][3] + by;
                if (mode == 1) {
                    v0 = fmaxf(v0, 0.f); v1 = fmaxf(v1, 0.f);
                    v2 = fmaxf(v2, 0.f); v3 = fmaxf(v3, 0.f);
                }
                *(float2*)(C + (size_t)(row + g    ) * CD + col) = make_float2(v0, v1);
                *(float2*)(C + (size_t)(row + g + 8) * CD + col) = make_float2(v2, v3);
            }
        }
    }
}

// ---------------------------------------------------------------------------
// Flash attention (causal), tf32 MMA, cp.async double-buffered K/V staging.
// CTA = (b, h, 128-row Q tile). 8 warps; warp w owns rows w*16..w*16+15.
// K/V arrive pre-converted to tf32 in 64x64 tiles -> pure cp.async staging.
// ---------------------------------------------------------------------------
#define KS_STR 68
#define VS_STR 72
#define PS_STR 68
#define BUF_U32 (64*KS_STR + 64*VS_STR)          // 8960
#define SMEM_ATTN ((2*BUF_U32 + 128*PS_STR) * 4) // 106,496 B

__global__ __launch_bounds__(256, 2)
void attn_mma_kernel(const float* __restrict__ Q, const uint32_t* __restrict__ Kt,
                     const uint32_t* __restrict__ Vt, float* __restrict__ CTX)
{
    extern __shared__ uint32_t sm_u[];
    const uint32_t sbase = (uint32_t)__cvta_generic_to_shared(sm_u);
    uint32_t* Ps = sm_u + 2*BUF_U32;

    const int tid  = threadIdx.x;
    const int lane = tid & 31;
    const int w    = tid >> 5;
    const int g    = lane >> 2;
    const int t    = lane & 3;

    const int qb = (CN/128 - 1) - blockIdx.x;   // heavy tiles first
    const int q0 = qb * 128;
    const int h = blockIdx.y, b = blockIdx.z;
    const size_t base = ((size_t)b * CN) * CD + (size_t)h * CHD;
    const size_t tile0 = (size_t)(b * CH + h) * NKT;

    const int rowA = q0 + w*16 + g;
    const int rowB = rowA + 8;

    // ---- Q fragments (scaled), registers for entire loop ----
    uint32_t qa[8][4];
    #pragma unroll
    for (int kc = 0; kc < 8; kc++) {
        int col = kc*8 + t;
        qa[kc][0] = f2tf32(Q[base + (size_t)rowA*CD + col    ] * 0.125f);
        qa[kc][1] = f2tf32(Q[base + (size_t)rowB*CD + col    ] * 0.125f);
        qa[kc][2] = f2tf32(Q[base + (size_t)rowA*CD + col + 4] * 0.125f);
        qa[kc][3] = f2tf32(Q[base + (size_t)rowB*CD + col + 4] * 0.125f);
    }

    float of[8][4];
    #pragma unroll
    for (int j = 0; j < 8; j++)
        #pragma unroll
        for (int e = 0; e < 4; e++) of[j][e] = 0.f;
    float mA = -1e30f, mB = -1e30f, lA = 0.f, lB = 0.f;

    const int nkt = 2*qb + 2;

    // stage tile kt into buffer d (8x 16B cp.async per thread)
    auto stage = [&](int kt, int d) {
        const uint32_t* gK = Kt + (tile0 + kt) * 4096;
        const uint32_t* gV = Vt + (tile0 + kt) * 4096;
        uint32_t ks = sbase + (uint32_t)d * (BUF_U32 * 4);
        uint32_t vs = ks + 64*KS_STR*4;
        #pragma unroll
        for (int p = 0; p < 4; p++) {
            int f = tid + 256*p;
            int r = f >> 4, c4 = (f & 15) * 4;
            cp16(ks + (r*KS_STR + c4)*4, gK + r*64 + c4);
            cp16(vs + (r*VS_STR + c4)*4, gV + r*64 + c4);
        }
        asm volatile("cp.async.commit_group;");
    };

    stage(0, 0);

    for (int kt = 0; kt < nkt; kt++) {
        asm volatile("cp.async.wait_group 0;");
        __syncthreads();
        if (kt + 1 < nkt) stage(kt + 1, (kt + 1) & 1);

        if (kt*64 > q0 + w*16 + 15) continue;   // warp fully above diagonal

        uint32_t* Ks = sm_u + (kt & 1) * BUF_U32;
        uint32_t* Vs = Ks + 64*KS_STR;

        // ---- S = Q K^T (16x64 per warp) ----
        float sc[8][4];
        #pragma unroll
        for (int j = 0; j < 8; j++)
            #pragma unroll
            for (int e = 0; e < 4; e++) sc[j][e] = 0.f;

        #pragma unroll
        for (int kc = 0; kc < 8; kc++) {
            #pragma unroll
            for (int j = 0; j < 8; j++) {
                uint32_t b0 = Ks[(j*8 + g)*KS_STR + kc*8 + t];
                uint32_t b1 = Ks[(j*8 + g)*KS_STR + kc*8 + t + 4];
                mma_tf32(sc[j], qa[kc][0], qa[kc][1], qa[kc][2], qa[kc][3], b0, b1);
            }
        }

        if (kt*64 + 63 > q0 + w*16) {   // diagonal-overlapping: mask
            #pragma unroll
            for (int j = 0; j < 8; j++) {
                int c0 = kt*64 + j*8 + t*2;
                int c1 = c0 + 1;
                if (c0 > rowA) sc[j][0] = -1e30f;
                if (c1 > rowA) sc[j][1] = -1e30f;
                if (c0 > rowB) sc[j][2] = -1e30f;
                if (c1 > rowB) sc[j][3] = -1e30f;
            }
        }

        // ---- online softmax (rows rowA, rowB; warp-local) ----
        float mxA = -1e30f, mxB = -1e30f;
        #pragma unroll
        for (int j = 0; j < 8; j++) {
            mxA = fmaxf(mxA, fmaxf(sc[j][0], sc[j][1]));
            mxB = fmaxf(mxB, fmaxf(sc[j][2], sc[j][3]));
        }
        mxA = fmaxf(mxA, __shfl_xor_sync(0xffffffffu, mxA, 1));
        mxA = fmaxf(mxA, __shfl_xor_sync(0xffffffffu, mxA, 2));
        mxB = fmaxf(mxB, __shfl_xor_sync(0xffffffffu, mxB, 1));
        mxB = fmaxf(mxB, __shfl_xor_sync(0xffffffffu, mxB, 2));

        float nmA = fmaxf(mA, mxA), nmB = fmaxf(mB, mxB);
        float alA = __expf(mA - nmA), alB = __expf(mB - nmB);
        mA = nmA; mB = nmB;

        float sumA = 0.f, sumB = 0.f;
        #pragma unroll
        for (int j = 0; j < 8; j++) {
            float p0 = __expf(sc[j][0] - mA);
            float p1 = __expf(sc[j][1] - mA);
            float p2 = __expf(sc[j][2] - mB);
            float p3 = __expf(sc[j][3] - mB);
            sumA += p0 + p1;
            sumB += p2 + p3;
            uint32_t* pr0 = &Ps[(w*16 + g    )*PS_STR + j*8 + t*2];
            uint32_t* pr1 = &Ps[(w*16 + g + 8)*PS_STR + j*8 + t*2];
            pr0[0] = f2tf32(p0); pr0[1] = f2tf32(p1);
            pr1[0] = f2tf32(p2); pr1[1] = f2tf32(p3);
        }
        sumA += __shfl_xor_sync(0xffffffffu, sumA, 1);
        sumA += __shfl_xor_sync(0xffffffffu, sumA, 2);
        sumB += __shfl_xor_sync(0xffffffffu, sumB, 1);
        sumB += __shfl_xor_sync(0xffffffffu, sumB, 2);
        lA = lA * alA + sumA;
        lB = lB * alB + sumB;

        #pragma unroll
        for (int j = 0; j < 8; j++) {
            of[j][0] *= alA; of[j][1] *= alA;
            of[j][2] *= alB; of[j][3] *= alB;
        }
        __syncwarp();

        // ---- O += P V ----
        #pragma unroll
        for (int kc = 0; kc < 8; kc++) {
            uint32_t a0 = Ps[(w*16 + g    )*PS_STR + kc*8 + t    ];
            uint32_t a1 = Ps[(w*16 + g + 8)*PS_STR + kc*8 + t    ];
            uint32_t a2 = Ps[(w*16 + g    )*PS_STR + kc*8 + t + 4];
            uint32_t a3 = Ps[(w*16 + g + 8)*PS_STR + kc*8 + t + 4];
            #pragma unroll
            for (int j = 0; j < 8; j++) {
                uint32_t b0 = Vs[(kc*8 + t    )*VS_STR + j*8 + g];
                uint32_t b1 = Vs[(kc*8 + t + 4)*VS_STR + j*8 + g];
                mma_tf32(of[j], a0, a1, a2, a3, b0, b1);
            }
        }
    }

    float invA = 1.f / lA, invB = 1.f / lB;
    #pragma unroll
    for (int j = 0; j < 8; j++) {
        float2 oA = make_float2(of[j][0]*invA, of[j][1]*invA);
        float2 oB = make_float2(of[j][2]*invB, of[j][3]*invB);
        *(float2*)(CTX + base + (size_t)rowA*CD + j*8 + t*2) = oA;
        *(float2*)(CTX + base + (size_t)rowB*CD + j*8 + t*2) = oB;
    }
}

// ---------------------------------------------------------------------------
extern "C" void kernel_launch(void* const* d_in, const int* in_sizes, int n_in,
                              void* d_out, int out_size)
{
    const float* x  = (const float*)d_in[0];
    // d_in[1] = causal_mask: unused (tril by construction; handled analytically)
    const float* Wq = (const float*)d_in[2];
    const float* bq = (const float*)d_in[3];
    const float* Wk = (const float*)d_in[4];
    const float* bk = (const float*)d_in[5];
    const float* Wv = (const float*)d_in[6];
    const float* bv = (const float*)d_in[7];
    const float* Wo = (const float*)d_in[8];
    const float* bo = (const float*)d_in[9];
    const float* Wu = (const float*)d_in[10];
    const float* bu = (const float*)d_in[11];
    float* out = (float*)d_out;

    float *Qb, *Cb, *Mb;
    uint32_t *Ktb, *Vtb;
    cudaGetSymbolAddress((void**)&Qb,  g_Q);
    cudaGetSymbolAddress((void**)&Ktb, g_Kt);
    cudaGetSymbolAddress((void**)&Vtb, g_Vt);
    cudaGetSymbolAddress((void**)&Cb,  g_CTX);
    cudaGetSymbolAddress((void**)&Mb,  g_MSG);

    cudaFuncSetAttribute(attn_mma_kernel,
                         cudaFuncAttributeMaxDynamicSharedMemorySize, SMEM_ATTN);

    dim3 gg(CM/128, CD/128);   // 128 x 2

    gemm_tf32_kernel<<<gg, 256>>>(x, x, Wq, bq, Qb, 256, 256, 0);
    gemm_tf32_kernel<<<gg, 256>>>(x, x, Wk, bk, (float*)Ktb, 256, 256, 2);
    gemm_tf32_kernel<<<gg, 256>>>(x, x, Wv, bv, (float*)Vtb, 256, 256, 2);

    attn_mma_kernel<<<dim3(CN/128, CH, CB), 256, SMEM_ATTN>>>(Qb, Ktb, Vtb, Cb);

    gemm_tf32_kernel<<<gg, 256>>>(Cb, Cb, Wo, bo, Mb, 256, 256, 0);
    gemm_tf32_kernel<<<gg, 256>>>(x, Mb, Wu, bu, out, 256, 512, 1);
}

// round 5
// speedup vs baseline: 3.4826x; 1.0329x over previous
#include <cuda_runtime.h>
#include <cstdint>

#define CB 8
#define CN 2048
#define CD 256
#define CH 4
#define CHD 64
#define CM (CB*CN)      // 16384 rows
#define NKT (CN/64)     // 32 key tiles per (b,h)

// Scratch (allocation-free rule: __device__ globals). All tf32 bit buffers.
__device__ uint32_t g_xt [CM*CD];     // x as tf32 bits, row-major
__device__ uint32_t g_wq [CD*CD];
__device__ uint32_t g_wk [CD*CD];
__device__ uint32_t g_wv [CD*CD];
__device__ uint32_t g_wo [CD*CD];
__device__ uint32_t g_wu [2*CD*CD];
__device__ uint32_t g_Qp [CM*CD];     // Q packed in mma A-frag order (scaled)
__device__ uint32_t g_Kp [CM*CD];     // K packed in S-mma B-frag order
__device__ uint32_t g_Vp [CM*CD];     // V packed in PV-mma B-frag order
__device__ uint32_t g_CTX[CM*CD];     // attention out, tf32 bits row-major
__device__ uint32_t g_MSG[CM*CD];     // messages, tf32 bits row-major

// ---------------------------------------------------------------------------
// helpers
// ---------------------------------------------------------------------------
__device__ __forceinline__ uint32_t f2tf32(float f) {
    uint32_t u;
    asm("cvt.rna.tf32.f32 %0, %1;" : "=r"(u) : "f"(f));
    return u;
}

__device__ __forceinline__ void mma_tf32(float c[4],
                                         uint32_t a0, uint32_t a1, uint32_t a2, uint32_t a3,
                                         uint32_t b0, uint32_t b1)
{
    asm volatile(
        "mma.sync.aligned.m16n8k8.row.col.f32.tf32.tf32.f32 "
        "{%0,%1,%2,%3}, {%4,%5,%6,%7}, {%8,%9}, {%0,%1,%2,%3};\n"
        : "+f"(c[0]), "+f"(c[1]), "+f"(c[2]), "+f"(c[3])
        : "r"(a0), "r"(a1), "r"(a2), "r"(a3), "r"(b0), "r"(b1));
}

__device__ __forceinline__ void cp16(uint32_t smem_addr, const void* gptr) {
    asm volatile("cp.async.cg.shared.global [%0], [%1], 16;"
                 :: "r"(smem_addr), "l"(gptr));
}

// ---- packed-layout index helpers (u32 index) ------------------------------
// K tile (64 keys x 64 d): frag (kc,jp), lane g*4+t, slots {b0(2jp),b1(2jp),b0(2jp+1),b1(2jp+1)}
__device__ __forceinline__ size_t k_pack_idx(int m, int col) {
    int b = m >> 11, key = m & 2047;
    int kt = key >> 6, kp = key & 63;
    int h = col >> 6, d = col & 63;
    int g = kp & 7, jb = kp >> 3;
    int kc = d >> 3, dt = d & 7, t = dt & 3;
    int slot = ((jb & 1) << 1) | (dt >> 2);
    int lane = (g << 2) | t;
    size_t tile = (size_t)(b*CH + h) * NKT + kt;
    return tile*4096 + (size_t)((((kc<<2) | (jb>>1))<<7) + (lane<<2) + slot);
}
__device__ __forceinline__ size_t v_pack_idx(int m, int col) {
    int b = m >> 11, key = m & 2047;
    int kt = key >> 6, kp = key & 63;
    int h = col >> 6, d = col & 63;
    int g = d & 7, jb = d >> 3;
    int kc = kp >> 3, kt8 = kp & 7, t = kt8 & 3;
    int slot = ((jb & 1) << 1) | (kt8 >> 2);
    int lane = (g << 2) | t;
    size_t tile = (size_t)(b*CH + h) * NKT + kt;
    return tile*4096 + (size_t)((((kc<<2) | (jb>>1))<<7) + (lane<<2) + slot);
}
__device__ __forceinline__ size_t q_pack_idx(int m, int col) {
    int tile16 = m >> 4, rr = m & 15;
    int g = rr & 7, half = rr >> 3;
    int h = col >> 6, d = col & 63;
    int kc = d >> 3, dt = d & 7, t = dt & 3;
    int slot = half | ((dt >> 2) << 1);
    int lane = (g << 2) | t;
    return (((size_t)tile16*CH + h)*8 + kc)*128 + (lane<<2) + slot;
}

// ---------------------------------------------------------------------------
// cvt kernel: fp32 -> tf32 bits for x and all weights (one pass)
// ---------------------------------------------------------------------------
__global__ void cvt_kernel(const float* __restrict__ x,  const float* __restrict__ Wq,
                           const float* __restrict__ Wk, const float* __restrict__ Wv,
                           const float* __restrict__ Wo, const float* __restrict__ Wu,
                           uint32_t* xt, uint32_t* wq, uint32_t* wk,
                           uint32_t* wv, uint32_t* wo, uint32_t* wu)
{
    int i = blockIdx.x * 256 + threadIdx.x;
    if (i < CM*CD) { xt[i] = f2tf32(x[i]); return; }
    i -= CM*CD;
    if (i < CD*CD) { wq[i] = f2tf32(Wq[i]); return; }
    i -= CD*CD;
    if (i < CD*CD) { wk[i] = f2tf32(Wk[i]); return; }
    i -= CD*CD;
    if (i < CD*CD) { wv[i] = f2tf32(Wv[i]); return; }
    i -= CD*CD;
    if (i < CD*CD) { wo[i] = f2tf32(Wo[i]); return; }
    i -= CD*CD;
    wu[i] = f2tf32(Wu[i]);
}
#define CVT_TOTAL (CM*CD + 5*CD*CD + CD*CD)   // x + 4 W + Wu(2 blocks)

// ---------------------------------------------------------------------------
// tf32 GEMM, all-tf32 inputs, cp.async double-buffered.
// CTA 128x128, BK=32, 8 warps, warp tile 64x32.
// mode: 0 = fp32 out + ReLU (final); 1 = tf32 bits row-major (MSG);
//       2 = packed K; 3 = packed V; 4 = packed Q (x0.125 scale).
// ---------------------------------------------------------------------------
#define GA_U32 4608          // 128*36
#define GB_U32 4352          // 32*136
#define GSMEM ((2*GA_U32 + 2*GB_U32) * 4)   // 71,680 B

__global__ __launch_bounds__(256, 2)
void gemm_tt_kernel(const uint32_t* __restrict__ A, const uint32_t* __restrict__ A2,
                    const uint32_t* __restrict__ W, const float* __restrict__ bias,
                    void* __restrict__ Cout, int K1, int Ktot, int mode)
{
    extern __shared__ uint32_t gsm[];
    const uint32_t sbase = (uint32_t)__cvta_generic_to_shared(gsm);

    const int tid  = threadIdx.x;
    const int lane = tid & 31;
    const int w    = tid >> 5;
    const int g    = lane >> 2;
    const int t    = lane & 3;
    const int m0 = blockIdx.x * 128;
    const int n0 = blockIdx.y * 128;
    const int warpM = (w >> 2) * 64;
    const int warpN = (w & 3) * 32;

    float acc[4][4][4];
    #pragma unroll
    for (int mi = 0; mi < 4; mi++)
        #pragma unroll
        for (int ni = 0; ni < 4; ni++)
            #pragma unroll
            for (int e = 0; e < 4; e++) acc[mi][ni][e] = 0.f;

    auto stage = [&](int c, int d) {
        int k0 = c * 32;
        const uint32_t* src; int ld;
        if (k0 < K1) { src = A + k0;        ld = K1;        }
        else         { src = A2 + (k0-K1);  ld = Ktot - K1; }
        uint32_t abase = sbase + (uint32_t)d * (GA_U32*4);
        uint32_t bbase = sbase + (2*GA_U32 + (uint32_t)d * GB_U32) * 4;
        #pragma unroll
        for (int u = 0; u < 4; u++) {
            int f = tid + 256*u;
            int r = f >> 3, c4 = f & 7;
            cp16(abase + (r*36 + c4*4)*4, src + (size_t)(m0 + r) * ld + c4*4);
        }
        #pragma unroll
        for (int u = 0; u < 4; u++) {
            int f = tid + 256*u;
            int kr = f >> 5, c4 = f & 31;
            cp16(bbase + (kr*136 + c4*4)*4, W + (size_t)(k0 + kr) * CD + n0 + c4*4);
        }
        asm volatile("cp.async.commit_group;");
    };

    const int nc = Ktot / 32;
    stage(0, 0);

    for (int c = 0; c < nc; c++) {
        asm volatile("cp.async.wait_group 0;");
        __syncthreads();
        if (c + 1 < nc) stage(c + 1, (c + 1) & 1);

        const uint32_t* As = gsm + (c & 1) * GA_U32;
        const uint32_t* Bs = gsm + 2*GA_U32 + (c & 1) * GB_U32;

        #pragma unroll
        for (int kk = 0; kk < 32; kk += 8) {
            uint32_t af[4][4];
            #pragma unroll
            for (int mi = 0; mi < 4; mi++) {
                int m = warpM + mi*16;
                af[mi][0] = As[(m + g    )*36 + kk + t    ];
                af[mi][1] = As[(m + g + 8)*36 + kk + t    ];
                af[mi][2] = As[(m + g    )*36 + kk + t + 4];
                af[mi][3] = As[(m + g + 8)*36 + kk + t + 4];
            }
            uint32_t bf[4][2];
            #pragma unroll
            for (int ni = 0; ni < 4; ni++) {
                int n = warpN + ni*8;
                bf[ni][0] = Bs[(kk + t    )*136 + n + g];
                bf[ni][1] = Bs[(kk + t + 4)*136 + n + g];
            }
            #pragma unroll
            for (int mi = 0; mi < 4; mi++)
                #pragma unroll
                for (int ni = 0; ni < 4; ni++)
                    mma_tf32(acc[mi][ni], af[mi][0], af[mi][1], af[mi][2], af[mi][3],
                             bf[ni][0], bf[ni][1]);
        }
    }

    // ---- epilogue by mode ----
    #pragma unroll
    for (int ni = 0; ni < 4; ni++) {
        int col0 = n0 + warpN + ni*8 + t*2;
        int col1 = col0 + 1;
        float bx = bias[col0], by = bias[col1];
        #pragma unroll
        for (int mi = 0; mi < 4; mi++) {
            int row0 = m0 + warpM + mi*16 + g;
            int row1 = row0 + 8;
            float e0 = acc[mi][ni][0] + bx;
            float e1 = acc[mi][ni][1] + by;
            float e2 = acc[mi][ni][2] + bx;
            float e3 = acc[mi][ni][3] + by;
            if (mode == 0) {
                float* C = (float*)Cout;
                *(float2*)(C + (size_t)row0*CD + col0) =
                    make_float2(fmaxf(e0, 0.f), fmaxf(e1, 0.f));
                *(float2*)(C + (size_t)row1*CD + col0) =
                    make_float2(fmaxf(e2, 0.f), fmaxf(e3, 0.f));
            } else if (mode == 1) {
                uint32_t* C = (uint32_t*)Cout;
                *(uint2*)(C + (size_t)row0*CD + col0) =
                    make_uint2(f2tf32(e0), f2tf32(e1));
                *(uint2*)(C + (size_t)row1*CD + col0) =
                    make_uint2(f2tf32(e2), f2tf32(e3));
            } else if (mode == 2) {
                uint32_t* C = (uint32_t*)Cout;
                C[k_pack_idx(row0, col0)] = f2tf32(e0);
                C[k_pack_idx(row0, col1)] = f2tf32(e1);
                C[k_pack_idx(row1, col0)] = f2tf32(e2);
                C[k_pack_idx(row1, col1)] = f2tf32(e3);
            } else if (mode == 3) {
                uint32_t* C = (uint32_t*)Cout;
                C[v_pack_idx(row0, col0)] = f2tf32(e0);
                C[v_pack_idx(row0, col1)] = f2tf32(e1);
                C[v_pack_idx(row1, col0)] = f2tf32(e2);
                C[v_pack_idx(row1, col1)] = f2tf32(e3);
            } else {
                uint32_t* C = (uint32_t*)Cout;
                C[q_pack_idx(row0, col0)] = f2tf32(e0 * 0.125f);
                C[q_pack_idx(row0, col1)] = f2tf32(e1 * 0.125f);
                C[q_pack_idx(row1, col0)] = f2tf32(e2 * 0.125f);
                C[q_pack_idx(row1, col1)] = f2tf32(e3 * 0.125f);
            }
        }
    }
}

// ---------------------------------------------------------------------------
// Flash attention (causal), tf32 MMA.
// Frag-packed K/V (LDS.128 fragment loads), packed Q (LDG.128),
// P via warp shuffles (no smem round trip), cp.async double-buffered K/V.
// CTA = (b, h, 128-row Q tile); warp w owns rows w*16..w*16+15.
// ---------------------------------------------------------------------------
#define TILE_U32 4096
#define ABUF_U32 (2*TILE_U32)                 // K tile + V tile
#define SMEM_ATTN (2*ABUF_U32*4)              // 65,536 B

__global__ __launch_bounds__(256, 2)
void attn_mma_kernel(const uint32_t* __restrict__ Qp, const uint32_t* __restrict__ Kp,
                     const uint32_t* __restrict__ Vp, uint32_t* __restrict__ CTX)
{
    extern __shared__ uint32_t sm_u[];
    const uint32_t sbase = (uint32_t)__cvta_generic_to_shared(sm_u);

    const int tid  = threadIdx.x;
    const int lane = tid & 31;
    const int w    = tid >> 5;
    const int g    = lane >> 2;
    const int t    = lane & 3;

    const int qb = (CN/128 - 1) - blockIdx.x;   // heavy tiles first
    const int q0 = qb * 128;
    const int h = blockIdx.y, b = blockIdx.z;
    const size_t tile0 = (size_t)(b*CH + h) * NKT;

    const int rowA = q0 + w*16 + g;
    const int rowB = rowA + 8;

    // ---- Q fragments: 8x LDG.128 from packed Q ----
    uint4 qa[8];
    {
        const uint32_t* qbase =
            Qp + (((size_t)(b*128 + (q0 >> 4) + w)*CH + h) * 8) * 128 + lane*4;
        #pragma unroll
        for (int kc = 0; kc < 8; kc++)
            qa[kc] = *(const uint4*)(qbase + kc*128);
    }

    float of[8][4];
    #pragma unroll
    for (int j = 0; j < 8; j++)
        #pragma unroll
        for (int e = 0; e < 4; e++) of[j][e] = 0.f;
    float mA = -1e30f, mB = -1e30f, lA = 0.f, lB = 0.f;

    const int nkt = 2*qb + 2;

    auto stage = [&](int kt, int d) {
        const uint32_t* gK = Kp + (tile0 + kt) * TILE_U32;
        const uint32_t* gV = Vp + (tile0 + kt) * TILE_U32;
        uint32_t ks = sbase + (uint32_t)d * (ABUF_U32*4);
        uint32_t vs = ks + TILE_U32*4;
        #pragma unroll
        for (int p = 0; p < 4; p++) {
            int idx = tid + 256*p;
            cp16(ks + idx*16, gK + idx*4);
            cp16(vs + idx*16, gV + idx*4);
        }
        asm volatile("cp.async.commit_group;");
    };

    stage(0, 0);

    for (int kt = 0; kt < nkt; kt++) {
        asm volatile("cp.async.wait_group 0;");
        __syncthreads();
        if (kt + 1 < nkt) stage(kt + 1, (kt + 1) & 1);

        if (kt*64 > q0 + w*16 + 15) continue;   // warp fully above diagonal

        const uint32_t* Ks = sm_u + (kt & 1) * ABUF_U32;
        const uint32_t* Vs = Ks + TILE_U32;

        // ---- S = Q K^T (16x64 per warp); frag loads via LDS.128 ----
        float sc[8][4];
        #pragma unroll
        for (int j = 0; j < 8; j++)
            #pragma unroll
            for (int e = 0; e < 4; e++) sc[j][e] = 0.f;

        #pragma unroll
        for (int kc = 0; kc < 8; kc++) {
            #pragma unroll
            for (int jp = 0; jp < 4; jp++) {
                uint4 kf = *(const uint4*)(Ks + (kc*4 + jp)*128 + lane*4);
                mma_tf32(sc[2*jp    ], qa[kc].x, qa[kc].y, qa[kc].z, qa[kc].w, kf.x, kf.y);
                mma_tf32(sc[2*jp + 1], qa[kc].x, qa[kc].y, qa[kc].z, qa[kc].w, kf.z, kf.w);
            }
        }

        if (kt*64 + 63 > q0 + w*16) {   // diagonal-overlapping: mask
            #pragma unroll
            for (int j = 0; j < 8; j++) {
                int c0 = kt*64 + j*8 + t*2;
                int c1 = c0 + 1;
                if (c0 > rowA) sc[j][0] = -1e30f;
                if (c1 > rowA) sc[j][1] = -1e30f;
                if (c0 > rowB) sc[j][2] = -1e30f;
                if (c1 > rowB) sc[j][3] = -1e30f;
            }
        }

        // ---- online softmax (rows rowA/rowB; warp-local) ----
        float mxA = -1e30f, mxB = -1e30f;
        #pragma unroll
        for (int j = 0; j < 8; j++) {
            mxA = fmaxf(mxA, fmaxf(sc[j][0], sc[j][1]));
            mxB = fmaxf(mxB, fmaxf(sc[j][2], sc[j][3]));
        }
        mxA = fmaxf(mxA, __shfl_xor_sync(0xffffffffu, mxA, 1));
        mxA = fmaxf(mxA, __shfl_xor_sync(0xffffffffu, mxA, 2));
        mxB = fmaxf(mxB, __shfl_xor_sync(0xffffffffu, mxB, 1));
        mxB = fmaxf(mxB, __shfl_xor_sync(0xffffffffu, mxB, 2));

        float nmA = fmaxf(mA, mxA), nmB = fmaxf(mB, mxB);
        float alA = __expf(mA - nmA), alB = __expf(mB - nmB);
        mA = nmA; mB = nmB;

        float sumA = 0.f, sumB = 0.f;
        #pragma unroll
        for (int j = 0; j < 8; j++) {
            sc[j][0] = __expf(sc[j][0] - mA);
            sc[j][1] = __expf(sc[j][1] - mA);
            sc[j][2] = __expf(sc[j][2] - mB);
            sc[j][3] = __expf(sc[j][3] - mB);
            sumA += sc[j][0] + sc[j][1];
            sumB += sc[j][2] + sc[j][3];
        }
        sumA += __shfl_xor_sync(0xffffffffu, sumA, 1);
        sumA += __shfl_xor_sync(0xffffffffu, sumA, 2);
        sumB += __shfl_xor_sync(0xffffffffu, sumB, 1);
        sumB += __shfl_xor_sync(0xffffffffu, sumB, 2);
        lA = lA * alA + sumA;
        lB = lB * alB + sumB;

        #pragma unroll
        for (int j = 0; j < 8; j++) {
            of[j][0] *= alA; of[j][1] *= alA;
            of[j][2] *= alB; of[j][3] *= alB;
        }

        // ---- O += P V; P fragments via in-warp shuffle permutation ----
        const int srcA = (lane & ~3) | (t >> 1);
        const int srcB = srcA + 2;
        const bool odd = (t & 1);
        #pragma unroll
        for (int kc = 0; kc < 8; kc++) {
            float x0 = __shfl_sync(0xffffffffu, sc[kc][0], srcA);
            float x1 = __shfl_sync(0xffffffffu, sc[kc][1], srcA);
            float y0 = __shfl_sync(0xffffffffu, sc[kc][0], srcB);
            float y1 = __shfl_sync(0xffffffffu, sc[kc][1], srcB);
            float z0 = __shfl_sync(0xffffffffu, sc[kc][2], srcA);
            float z1 = __shfl_sync(0xffffffffu, sc[kc][3], srcA);
            float w0 = __shfl_sync(0xffffffffu, sc[kc][2], srcB);
            float w1 = __shfl_sync(0xffffffffu, sc[kc][3], srcB);
            uint32_t a0 = f2tf32(odd ? x1 : x0);
            uint32_t a2 = f2tf32(odd ? y1 : y0);
            uint32_t a1 = f2tf32(odd ? z1 : z0);
            uint32_t a3 = f2tf32(odd ? w1 : w0);
            #pragma unroll
            for (int jp = 0; jp < 4; jp++) {
                uint4 vf = *(const uint4*)(Vs + (kc*4 + jp)*128 + lane*4);
                mma_tf32(of[2*jp    ], a0, a1, a2, a3, vf.x, vf.y);
                mma_tf32(of[2*jp + 1], a0, a1, a2, a3, vf.z, vf.w);
            }
        }
    }

    // ---- epilogue: normalize, write CTX as tf32 bits ([B*N, D]) ----
    const size_t base = ((size_t)b * CN) * CD + (size_t)h * CHD;
    float invA = 1.f / lA, invB = 1.f / lB;
    #pragma unroll
    for (int j = 0; j < 8; j++) {
        *(uint2*)(CTX + base + (size_t)rowA*CD + j*8 + t*2) =
            make_uint2(f2tf32(of[j][0]*invA), f2tf32(of[j][1]*invA));
        *(uint2*)(CTX + base + (size_t)rowB*CD + j*8 + t*2) =
            make_uint2(f2tf32(of[j][2]*invB), f2tf32(of[j][3]*invB));
    }
}

// ---------------------------------------------------------------------------
extern "C" void kernel_launch(void* const* d_in, const int* in_sizes, int n_in,
                              void* d_out, int out_size)
{
    const float* x  = (const float*)d_in[0];
    // d_in[1] = causal_mask: unused (tril by construction; handled analytically)
    const float* Wq = (const float*)d_in[2];
    const float* bq = (const float*)d_in[3];
    const float* Wk = (const float*)d_in[4];
    const float* bk = (const float*)d_in[5];
    const float* Wv = (const float*)d_in[6];
    const float* bv = (const float*)d_in[7];
    const float* Wo = (const float*)d_in[8];
    const float* bo = (const float*)d_in[9];
    const float* Wu = (const float*)d_in[10];
    const float* bu = (const float*)d_in[11];
    float* out = (float*)d_out;

    uint32_t *xt, *wq, *wk, *wv, *wo, *wu, *Qp, *Kpp, *Vpp, *Cb, *Mb;
    cudaGetSymbolAddress((void**)&xt,  g_xt);
    cudaGetSymbolAddress((void**)&wq,  g_wq);
    cudaGetSymbolAddress((void**)&wk,  g_wk);
    cudaGetSymbolAddress((void**)&wv,  g_wv);
    cudaGetSymbolAddress((void**)&wo,  g_wo);
    cudaGetSymbolAddress((void**)&wu,  g_wu);
    cudaGetSymbolAddress((void**)&Qp,  g_Qp);
    cudaGetSymbolAddress((void**)&Kpp, g_Kp);
    cudaGetSymbolAddress((void**)&Vpp, g_Vp);
    cudaGetSymbolAddress((void**)&Cb,  g_CTX);
    cudaGetSymbolAddress((void**)&Mb,  g_MSG);

    cudaFuncSetAttribute(gemm_tt_kernel,
                         cudaFuncAttributeMaxDynamicSharedMemorySize, GSMEM);
    cudaFuncSetAttribute(attn_mma_kernel,
                         cudaFuncAttributeMaxDynamicSharedMemorySize, SMEM_ATTN);

    // 1) convert x + weights to tf32 bits
    cvt_kernel<<<CVT_TOTAL/256, 256>>>(x, Wq, Wk, Wv, Wo, Wu, xt, wq, wk, wv, wo, wu);

    dim3 gg(CM/128, CD/128);   // 128 x 2

    // 2) projections (outputs packed for attention)
    gemm_tt_kernel<<<gg, 256, GSMEM>>>(xt, xt, wq, bq, Qp,  256, 256, 4);
    gemm_tt_kernel<<<gg, 256, GSMEM>>>(xt, xt, wk, bk, Kpp, 256, 256, 2);
    gemm_tt_kernel<<<gg, 256, GSMEM>>>(xt, xt, wv, bv, Vpp, 256, 256, 3);

    // 3) causal flash attention
    attn_mma_kernel<<<dim3(CN/128, CH, CB), 256, SMEM_ATTN>>>(Qp, Kpp, Vpp, Cb);

    // 4) output projection + update MLP (concat fused)
    gemm_tt_kernel<<<gg, 256, GSMEM>>>(Cb, Cb, wo, bo, Mb, 256, 256, 1);
    gemm_tt_kernel<<<gg, 256, GSMEM>>>(xt, Mb, wu, bu, out, 256, 512, 0);
}